// round 16
// baseline (speedup 1.0000x reference)
#include <cuda_runtime.h>

#define NDET    8192
#define ROW     85
#define IMG     640
#define CAP     128          // fast-path capacity (V ~ 77 expected)
#define W32     4            // 128/32 words per row
#define NBLK    128
#define NTHR    1024
#define ZPB4    80           // float4s zeroed per block (128*80*4 = 40960 floats)

// Global scratch (allocation-free rule). g_cnt/g_done zero at module load,
// reset by the NMS block every launch -> deterministic across graph replays.
__device__ int                g_cnt  = 0;
__device__ int                g_done = 0;
__device__ unsigned long long c_key[NDET];   // (conf_bits<<32) | ~det_idx
__device__ float4             c_box[NDET];
// slow-path (V > CAP) scratch only:
__device__ float  s_conf[NDET];
__device__ float4 s_box[NDET];

// ---------------------------------------------------------------------------
// Fused kernel: 128 blocks x 1024 threads = 1 block/SM, one balanced wave.
// Phase A: float4 output zeroing; each warp decodes 2 detections with batched
//   loads; class max via __reduce_max_sync (exact: scores non-negative fp32);
//   validity decided by ONE ballot over lane-local predicates (shuffles and
//   box math only on the rare valid path); compaction via atomicAdd storing
//   box + prebuilt 64-bit key.
// Handshake: single release-atomic done counter.
// Phase B (last arriving block), in ORIGINAL compacted space (no sort):
//   matrix row j: bit i set iff key_i > key_j && iou(i,j) > thres (acyclic);
//   rank_j from the same ballots; warp-0 Jacobi fixpoint (== greedy NMS);
//   survivors scattered to rank positions.
// ---------------------------------------------------------------------------
__global__ void __launch_bounds__(NTHR) yolo_fused(const float* __restrict__ x,
                                                   float* __restrict__ out) {
    const int t    = threadIdx.x;
    const int lane = t & 31;
    const int wid  = t >> 5;

    __shared__ float sx1[CAP], sy1[CAP], sx2[CAP], sy2[CAP], scf[CAP];
    __shared__ unsigned long long skey[CAP];
    __shared__ int srank[CAP];
    __shared__ unsigned int supT[CAP * W32];   // fast path: 2 KB
    __shared__ unsigned char keep8[NDET];      // slow path only (8 KB)
    __shared__ int sh_last;

    // ================= Phase A =================
    if (t < ZPB4)                                  // balanced float4 zeroing
        reinterpret_cast<float4*>(out)[blockIdx.x * ZPB4 + t] =
            make_float4(0.f, 0.f, 0.f, 0.f);

    {
        int det0 = blockIdx.x * 64 + wid;
        int det1 = det0 + 32;
        const float* r0 = x + (long)det0 * ROW;
        const float* r1 = x + (long)det1 * ROW;
        // batch all 6 independent loads (MLP = 6 per warp)
        float a0 = r0[lane];
        float a1 = r0[lane + 32];
        float a2 = (lane < 21) ? r0[lane + 64] : 0.0f;
        float e0 = r1[lane];
        float e1 = r1[lane + 32];
        float e2 = (lane < 21) ? r1[lane + 64] : 0.0f;

        // class max over positions 6..84; scores are uniform[0,1) >= 0 so
        // uint order == float order and 0.0f is a safe identity.
        float ma = (lane >= 6) ? a0 : 0.0f;
        ma = fmaxf(ma, a1); ma = fmaxf(ma, a2);
        float me = (lane >= 6) ? e0 : 0.0f;
        me = fmaxf(me, e1); me = fmaxf(me, e2);
        unsigned int mA = __reduce_max_sync(0xffffffffu, __float_as_uint(ma));
        unsigned int mE = __reduce_max_sync(0xffffffffu, __float_as_uint(me));

        #pragma unroll
        for (int pass = 0; pass < 2; pass++) {
            float src = pass ? e0 : a0;
            float m   = __uint_as_float(pass ? mE : mA);
            // validity via one ballot of lane-local predicates:
            //   lane 2: b2 > 0  (<=> w = 640*b2 > 0)
            //   lane 3: b3 > 0  (<=> h > 0)
            //   lane 4: conf > 0.25
            //   lane 5: cls0 >= max(classes 1..79)   (argmax == 0)
            bool pred =
                (lane == 5) ? (src >= m) :
                (lane == 4) ? (src > 0.25f) :
                (lane == 2 || lane == 3) ? (src > 0.0f) : false;
            unsigned int bal = __ballot_sync(0xffffffffu, pred);
            bool valid = ((bal & 0x30u) == 0x30u) && ((bal & 0x0Cu) != 0u);

            if (valid) {                       // warp-uniform, rare (~0.9%)
                float b0   = __shfl_sync(0xffffffffu, src, 0);
                float b1   = __shfl_sync(0xffffffffu, src, 1);
                float b2   = __shfl_sync(0xffffffffu, src, 2);
                float b3   = __shfl_sync(0xffffffffu, src, 3);
                float conf = __shfl_sync(0xffffffffu, src, 4);
                if (lane == 0) {
                    int det  = pass ? det1 : det0;
                    float cx = b0 * 640.0f, cy = b1 * 640.0f;
                    float w  = b2 * 640.0f, h  = b3 * 640.0f;
                    float hw = truncf(w * 0.5f);
                    float hh = truncf(h * 0.5f);
                    int x1 = (int)(cx - hw);
                    int y1 = (int)(cy - hh);
                    int x2 = (int)(cx + hw);
                    int y2 = (int)(cy + hh);
                    x1 = x1 > 0 ? x1 : 0;
                    y1 = y1 > 0 ? y1 : 0;
                    x2 = x2 < IMG ? x2 : IMG;
                    y2 = y2 < IMG ? y2 : IMG;
                    int slot = atomicAdd(&g_cnt, 1);
                    c_key[slot] = ((unsigned long long)__float_as_uint(conf)
                                   << 32) | (unsigned int)(~det);
                    c_box[slot] = make_float4((float)x1, (float)y1,
                                              (float)x2, (float)y2);
                }
            }
        }
    }

    // ---- handshake: release-atomic done counter; last block runs NMS ----
    __syncthreads();              // all block writes happen-before t0's atomic
    if (t == 0) {
        int prev;
        asm volatile("atom.add.release.gpu.s32 %0, [%1], 1;"
                     : "=r"(prev) : "l"(&g_done) : "memory");
        sh_last = (prev == NBLK - 1);
    }
    __syncthreads();
    if (!sh_last) return;
    asm volatile("fence.acq_rel.gpu;" ::: "memory");   // acquire side

    // ================= Phase B: NMS (single block) =================
    // Concurrent entry loads; lanes t >= V read stale-but-masked data.
    unsigned long long mykey = 0;
    float4 mb = make_float4(0.f, 0.f, 0.f, 0.f);
    if (t < CAP) {
        mykey = c_key[t];
        mb    = c_box[t];
    }
    if (t < CAP * W32) supT[t] = 0u;            // zero matrix upfront
    const int V = g_cnt;

    if (V <= CAP) {
        if (t < V) {
            skey[t] = mykey;
            sx1[t] = mb.x; sy1[t] = mb.y; sx2[t] = mb.z; sy2[t] = mb.w;
            scf[t] = __uint_as_float((unsigned int)(mykey >> 32));
        }
        __syncthreads();

        // ---- suppression matrix + rank, original space; warp per row j ----
        // bit i of supT[j][w]: key_i > key_j && iou(i,j) > thres
        // rank_j = #{i : key_i > key_j}
        const int nw = (V + 31) >> 5;
        for (int j = wid; j < V; j += 32) {
            unsigned long long kj = skey[j];
            float x1j = sx1[j], y1j = sy1[j], x2j = sx2[j], y2j = sy2[j];
            float areaj = (x2j - x1j) * (y2j - y1j);   // exact in fp32
            int r = 0;
            for (int w = 0; w < nw; w++) {
                int i = (w << 5) + lane;
                bool dir = false, sb = false;
                if (i < V) {
                    dir = skey[i] > kj;        // i ranks before j
                    if (dir) {
                        float x1i = sx1[i], y1i = sy1[i];
                        float x2i = sx2[i], y2i = sy2[i];
                        float iw = fmaxf(fminf(x2i, x2j) - fmaxf(x1i, x1j), 0.0f);
                        float ih = fmaxf(fminf(y2i, y2j) - fmaxf(y1i, y1j), 0.0f);
                        float inter = iw * ih;
                        float areai = (x2i - x1i) * (y2i - y1i);
                        float uni = areai + areaj - inter;
                        float iou = __fdiv_rn(inter, fmaxf(uni, 1e-9f)); // IEEE
                        sb = iou > 0.45f;
                    }
                }
                unsigned int dm   = __ballot_sync(0xffffffffu, dir);
                unsigned int bits = __ballot_sync(0xffffffffu, sb);
                r += __popc(dm);
                if (lane == 0) supT[j * W32 + w] = bits;
            }
            if (lane == 0) srank[j] = r;
        }
        __syncthreads();

        // ---- warp-0 Jacobi fixpoint (== greedy NMS; relation acyclic) ----
        if (wid == 0) {
            unsigned int rT[W32][W32];           // lane owns 4 rows
            #pragma unroll
            for (int k = 0; k < W32; k++) {
                int j = (k << 5) + lane;
                #pragma unroll
                for (int w = 0; w < W32; w++)
                    rT[k][w] = (j < V) ? supT[j * W32 + w] : 0u;
            }
            unsigned int kw[W32];                // alive mask (uniform)
            #pragma unroll
            for (int w = 0; w < W32; w++) {
                int rem = V - (w << 5);
                kw[w] = (rem >= 32) ? 0xFFFFFFFFu
                      : (rem <= 0)  ? 0u : ((1u << rem) - 1u);
            }
            for (int it = 0; it < CAP; it++) {   // expected ~3 iterations
                unsigned int nkw[W32];
                #pragma unroll
                for (int k = 0; k < W32; k++) {
                    int j = (k << 5) + lane;
                    unsigned int dead = (rT[k][0] & kw[0]) | (rT[k][1] & kw[1])
                                      | (rT[k][2] & kw[2]) | (rT[k][3] & kw[3]);
                    bool alive = (j < V) && (dead == 0u);
                    nkw[k] = __ballot_sync(0xffffffffu, alive);
                }
                unsigned int changed = 0u;       // uniform across lanes
                #pragma unroll
                for (int k = 0; k < W32; k++) {
                    changed |= nkw[k] ^ kw[k];
                    kw[k] = nkw[k];
                }
                if (changed == 0u) break;        // fixpoint == greedy result
            }
            // ---- scatter survivors to their rank positions ----
            #pragma unroll
            for (int k = 0; k < W32; k++) {
                int j = (k << 5) + lane;
                if (j < V && ((kw[k] >> lane) & 1u)) {
                    int r = srank[j];
                    out[4 * r + 0] = sx1[j];
                    out[4 * r + 1] = sy1[j];
                    out[4 * r + 2] = sx2[j];
                    out[4 * r + 3] = sy2[j];
                    out[NDET * 4 + r] = scf[j];
                }
            }
            if (lane == 0) { g_cnt = 0; g_done = 0; }   // reset for replay
        }
        // other warps exit; no trailing barrier needed
    } else {
        // ============ SLOW PATH (V > CAP; global arrays) ============
        __syncthreads();
        for (int i = t; i < V; i += NTHR) {
            unsigned long long ki = c_key[i];
            int r = 0;
            for (int j = 0; j < V; j++) r += (c_key[j] > ki);
            s_conf[r] = __uint_as_float((unsigned int)(ki >> 32));
            s_box[r]  = c_box[i];
        }
        __syncthreads();

        for (int i = t; i < NDET; i += NTHR) keep8[i] = 1;
        __syncthreads();
        for (int i = 0; i + 1 < V; i++) {
            if (keep8[i]) {
                float4 bi = s_box[i];
                float areai = (bi.z - bi.x) * (bi.w - bi.y);
                for (int j = i + 1 + t; j < V; j += NTHR) {
                    if (keep8[j]) {
                        float4 bj = s_box[j];
                        float iw = fmaxf(fminf(bi.z, bj.z) - fmaxf(bi.x, bj.x), 0.0f);
                        float ih = fmaxf(fminf(bi.w, bj.w) - fmaxf(bi.y, bj.y), 0.0f);
                        float inter = iw * ih;
                        float areaj = (bj.z - bj.x) * (bj.w - bj.y);
                        float uni = areai + areaj - inter;
                        float iou = __fdiv_rn(inter, fmaxf(uni, 1e-9f));
                        if (iou > 0.45f) keep8[j] = 0;
                    }
                }
            }
            __syncthreads();
        }
        for (int i = t; i < V; i += NTHR) {
            if (keep8[i]) {
                float4 b = s_box[i];
                out[4 * i + 0] = b.x;
                out[4 * i + 1] = b.y;
                out[4 * i + 2] = b.z;
                out[4 * i + 3] = b.w;
                out[NDET * 4 + i] = s_conf[i];
            }
        }
        if (t == 0) { g_cnt = 0; g_done = 0; }
    }
}

extern "C" void kernel_launch(void* const* d_in, const int* in_sizes, int n_in,
                              void* d_out, int out_size) {
    const float* x = (const float*)d_in[0];   // (1, 8192, 85) fp32
    float* out = (float*)d_out;               // 8192*4 boxes then 8192 scores
    yolo_fused<<<NBLK, NTHR>>>(x, out);
}

// round 17
// speedup vs baseline: 1.0748x; 1.0748x over previous
#include <cuda_runtime.h>

#define NDET    8192
#define ROW     85
#define IMG     640
#define CAP     128          // fast-path capacity (V ~ 77 expected)
#define W32     4            // 128/32 words per row
#define NBLK    128
#define NTHR    1024
#define ZPB     320          // output floats zeroed per block (128*320 = 40960)

// Global scratch (allocation-free rule). g_cnt/g_done zero at module load,
// reset by the NMS block every launch -> deterministic across graph replays.
__device__ int                g_cnt  = 0;
__device__ int                g_done = 0;
__device__ unsigned long long c_key[NDET];   // (conf_bits<<32) | ~det_idx
__device__ float4             c_box[NDET];
// slow-path (V > CAP) scratch only:
__device__ float  s_conf[NDET];
__device__ float4 s_box[NDET];

// ---------------------------------------------------------------------------
// Fused kernel: 128 blocks x 1024 threads = 1 block/SM, one balanced wave.
// Phase A: balanced output zeroing; each warp decodes 2 detections (batched
//   loads, __reduce_max_sync class max — exact for non-negative fp32); valid
//   dets compacted via atomicAdd, storing box + prebuilt 64-bit key.
// Handshake: single release-atomic done counter (syncthreads gives
//   happens-before from all block threads to t0's release atomic).
// Phase B (last arriving block), in ORIGINAL compacted space (no sort):
//   matrix row j: bit i set iff key_i > key_j && iou(i,j) > thres (acyclic);
//   rank_j from the same ballots; warp-0 Jacobi fixpoint (== greedy NMS);
//   survivors scattered to rank positions.
// ---------------------------------------------------------------------------
__global__ void __launch_bounds__(NTHR) yolo_fused(const float* __restrict__ x,
                                                   float* __restrict__ out) {
    const int t    = threadIdx.x;
    const int lane = t & 31;
    const int wid  = t >> 5;

    __shared__ float sx1[CAP], sy1[CAP], sx2[CAP], sy2[CAP], scf[CAP];
    __shared__ unsigned long long skey[CAP];
    __shared__ int srank[CAP];
    __shared__ unsigned int supT[CAP * W32];   // fast path: 2 KB
    __shared__ unsigned char keep8[NDET];      // slow path only (8 KB)
    __shared__ int sh_last;

    // ================= Phase A =================
    if (t < ZPB) out[blockIdx.x * ZPB + t] = 0.0f;   // balanced zeroing

    {
        int det0 = blockIdx.x * 64 + wid;
        int det1 = det0 + 32;
        const float* r0 = x + (long)det0 * ROW;
        const float* r1 = x + (long)det1 * ROW;
        // batch all 6 independent loads (MLP = 6 per warp)
        float a0 = r0[lane];
        float a1 = r0[lane + 32];
        float a2 = (lane < 21) ? r0[lane + 64] : 0.0f;
        float e0 = r1[lane];
        float e1 = r1[lane + 32];
        float e2 = (lane < 21) ? r1[lane + 64] : 0.0f;

        // class max over positions 6..84; scores are uniform[0,1) >= 0 so
        // uint order == float order and 0.0f is a safe identity.
        float ma = (lane >= 6) ? a0 : 0.0f;
        ma = fmaxf(ma, a1); ma = fmaxf(ma, a2);
        float me = (lane >= 6) ? e0 : 0.0f;
        me = fmaxf(me, e1); me = fmaxf(me, e2);
        unsigned int mA = __reduce_max_sync(0xffffffffu, __float_as_uint(ma));
        unsigned int mE = __reduce_max_sync(0xffffffffu, __float_as_uint(me));

        #pragma unroll
        for (int pass = 0; pass < 2; pass++) {
            float src  = pass ? e0 : a0;
            float b0   = __shfl_sync(0xffffffffu, src, 0);
            float b1   = __shfl_sync(0xffffffffu, src, 1);
            float b2   = __shfl_sync(0xffffffffu, src, 2);
            float b3   = __shfl_sync(0xffffffffu, src, 3);
            float conf = __shfl_sync(0xffffffffu, src, 4);
            float cls0 = __shfl_sync(0xffffffffu, src, 5);
            if (lane == 0) {
                float m = __uint_as_float(pass ? mE : mA);
                int det  = pass ? det1 : det0;
                float cx = b0 * 640.0f, cy = b1 * 640.0f;
                float w  = b2 * 640.0f, h  = b3 * 640.0f;
                // argmax==0 <=> cls0 >= max(later classes)
                if ((conf > 0.25f) && (cls0 >= m) &&
                    ((w > 0.0f) || (h > 0.0f))) {
                    float hw = truncf(w * 0.5f);
                    float hh = truncf(h * 0.5f);
                    int x1 = (int)(cx - hw);
                    int y1 = (int)(cy - hh);
                    int x2 = (int)(cx + hw);
                    int y2 = (int)(cy + hh);
                    x1 = x1 > 0 ? x1 : 0;
                    y1 = y1 > 0 ? y1 : 0;
                    x2 = x2 < IMG ? x2 : IMG;
                    y2 = y2 < IMG ? y2 : IMG;
                    int slot = atomicAdd(&g_cnt, 1);
                    c_key[slot] = ((unsigned long long)__float_as_uint(conf)
                                   << 32) | (unsigned int)(~det);
                    c_box[slot] = make_float4((float)x1, (float)y1,
                                              (float)x2, (float)y2);
                }
            }
        }
    }

    // ---- handshake: release-atomic done counter; last block runs NMS ----
    __syncthreads();              // all block writes happen-before t0's atomic
    if (t == 0) {
        int prev;
        asm volatile("atom.add.release.gpu.s32 %0, [%1], 1;"
                     : "=r"(prev) : "l"(&g_done) : "memory");
        sh_last = (prev == NBLK - 1);
    }
    __syncthreads();
    if (!sh_last) return;
    __threadfence();              // acquire: see all blocks' writes

    // ================= Phase B: NMS (single block) =================
    // Concurrent entry loads; lanes t >= V read stale-but-masked data.
    unsigned long long mykey = 0;
    float4 mb = make_float4(0.f, 0.f, 0.f, 0.f);
    if (t < CAP) {
        mykey = c_key[t];
        mb    = c_box[t];
    }
    if (t < CAP * W32) supT[t] = 0u;            // zero matrix upfront
    const int V = g_cnt;

    if (V <= CAP) {
        if (t < V) {
            skey[t] = mykey;
            sx1[t] = mb.x; sy1[t] = mb.y; sx2[t] = mb.z; sy2[t] = mb.w;
            scf[t] = __uint_as_float((unsigned int)(mykey >> 32));
        }
        __syncthreads();

        // ---- suppression matrix + rank, original space; warp per row j ----
        // bit i of supT[j][w]: key_i > key_j && iou(i,j) > thres
        // rank_j = #{i : key_i > key_j}
        const int nw = (V + 31) >> 5;
        for (int j = wid; j < V; j += 32) {
            unsigned long long kj = skey[j];
            float x1j = sx1[j], y1j = sy1[j], x2j = sx2[j], y2j = sy2[j];
            float areaj = (x2j - x1j) * (y2j - y1j);   // exact in fp32
            int r = 0;
            for (int w = 0; w < nw; w++) {
                int i = (w << 5) + lane;
                bool dir = false, sb = false;
                if (i < V) {
                    dir = skey[i] > kj;        // i ranks before j
                    if (dir) {
                        float x1i = sx1[i], y1i = sy1[i];
                        float x2i = sx2[i], y2i = sy2[i];
                        float iw = fmaxf(fminf(x2i, x2j) - fmaxf(x1i, x1j), 0.0f);
                        float ih = fmaxf(fminf(y2i, y2j) - fmaxf(y1i, y1j), 0.0f);
                        float inter = iw * ih;
                        float areai = (x2i - x1i) * (y2i - y1i);
                        float uni = areai + areaj - inter;
                        float iou = __fdiv_rn(inter, fmaxf(uni, 1e-9f)); // IEEE
                        sb = iou > 0.45f;
                    }
                }
                unsigned int dm   = __ballot_sync(0xffffffffu, dir);
                unsigned int bits = __ballot_sync(0xffffffffu, sb);
                r += __popc(dm);
                if (lane == 0) supT[j * W32 + w] = bits;
            }
            if (lane == 0) srank[j] = r;
        }
        __syncthreads();

        // ---- warp-0 Jacobi fixpoint (== greedy NMS; relation acyclic) ----
        if (wid == 0) {
            unsigned int rT[W32][W32];           // lane owns 4 rows
            #pragma unroll
            for (int k = 0; k < W32; k++) {
                int j = (k << 5) + lane;
                #pragma unroll
                for (int w = 0; w < W32; w++)
                    rT[k][w] = (j < V) ? supT[j * W32 + w] : 0u;
            }
            unsigned int kw[W32];                // alive mask (uniform)
            #pragma unroll
            for (int w = 0; w < W32; w++) {
                int rem = V - (w << 5);
                kw[w] = (rem >= 32) ? 0xFFFFFFFFu
                      : (rem <= 0)  ? 0u : ((1u << rem) - 1u);
            }
            for (int it = 0; it < CAP; it++) {   // expected ~3 iterations
                unsigned int nkw[W32];
                #pragma unroll
                for (int k = 0; k < W32; k++) {
                    int j = (k << 5) + lane;
                    unsigned int dead = (rT[k][0] & kw[0]) | (rT[k][1] & kw[1])
                                      | (rT[k][2] & kw[2]) | (rT[k][3] & kw[3]);
                    bool alive = (j < V) && (dead == 0u);
                    nkw[k] = __ballot_sync(0xffffffffu, alive);
                }
                unsigned int changed = 0u;       // uniform across lanes
                #pragma unroll
                for (int k = 0; k < W32; k++) {
                    changed |= nkw[k] ^ kw[k];
                    kw[k] = nkw[k];
                }
                if (changed == 0u) break;        // fixpoint == greedy result
            }
            // ---- scatter survivors to their rank positions ----
            #pragma unroll
            for (int k = 0; k < W32; k++) {
                int j = (k << 5) + lane;
                if (j < V && ((kw[k] >> lane) & 1u)) {
                    int r = srank[j];
                    out[4 * r + 0] = sx1[j];
                    out[4 * r + 1] = sy1[j];
                    out[4 * r + 2] = sx2[j];
                    out[4 * r + 3] = sy2[j];
                    out[NDET * 4 + r] = scf[j];
                }
            }
            if (lane == 0) { g_cnt = 0; g_done = 0; }   // reset for replay
        }
        // other warps exit; no trailing barrier needed
    } else {
        // ============ SLOW PATH (V > CAP; global arrays) ============
        __syncthreads();
        for (int i = t; i < V; i += NTHR) {
            unsigned long long ki = c_key[i];
            int r = 0;
            for (int j = 0; j < V; j++) r += (c_key[j] > ki);
            s_conf[r] = __uint_as_float((unsigned int)(ki >> 32));
            s_box[r]  = c_box[i];
        }
        __syncthreads();

        for (int i = t; i < NDET; i += NTHR) keep8[i] = 1;
        __syncthreads();
        for (int i = 0; i + 1 < V; i++) {
            if (keep8[i]) {
                float4 bi = s_box[i];
                float areai = (bi.z - bi.x) * (bi.w - bi.y);
                for (int j = i + 1 + t; j < V; j += NTHR) {
                    if (keep8[j]) {
                        float4 bj = s_box[j];
                        float iw = fmaxf(fminf(bi.z, bj.z) - fmaxf(bi.x, bj.x), 0.0f);
                        float ih = fmaxf(fminf(bi.w, bj.w) - fmaxf(bi.y, bj.y), 0.0f);
                        float inter = iw * ih;
                        float areaj = (bj.z - bj.x) * (bj.w - bj.y);
                        float uni = areai + areaj - inter;
                        float iou = __fdiv_rn(inter, fmaxf(uni, 1e-9f));
                        if (iou > 0.45f) keep8[j] = 0;
                    }
                }
            }
            __syncthreads();
        }
        for (int i = t; i < V; i += NTHR) {
            if (keep8[i]) {
                float4 b = s_box[i];
                out[4 * i + 0] = b.x;
                out[4 * i + 1] = b.y;
                out[4 * i + 2] = b.z;
                out[4 * i + 3] = b.w;
                out[NDET * 4 + i] = s_conf[i];
            }
        }
        if (t == 0) { g_cnt = 0; g_done = 0; }
    }
}

extern "C" void kernel_launch(void* const* d_in, const int* in_sizes, int n_in,
                              void* d_out, int out_size) {
    const float* x = (const float*)d_in[0];   // (1, 8192, 85) fp32
    float* out = (float*)d_out;               // 8192*4 boxes then 8192 scores
    yolo_fused<<<NBLK, NTHR>>>(x, out);
}